// round 1
// baseline (speedup 1.0000x reference)
#include <cuda_runtime.h>
#include <cuda_bf16.h>
#include <math.h>

// ---------------- problem constants ----------------
#define BATCH   2
#define SEQLEN  2048
#define DMODEL  768
#define DINNER  1536
#define DSTATE  16
#define DCONV   4
#define DTRANK  48
#define XDBLW   (DTRANK + 2*DSTATE)   // 80
#define MROWS   (BATCH*SEQLEN)        // 4096

// ---------------- scratch (no allocs allowed) ----------------
__device__ float g_xz  [(size_t)MROWS * 2*DINNER];  // in_proj output (x | z)
__device__ float g_xc  [(size_t)MROWS * DINNER];    // conv+silu output
__device__ float g_xdbl[(size_t)MROWS * XDBLW];     // dt_raw | B | C
__device__ float g_dt  [(size_t)MROWS * DINNER];    // softplus(dt_proj)
__device__ float g_y   [(size_t)MROWS * DINNER];    // scan out / combined
__device__ float g_q   [(size_t)MROWS * DINNER];    // query proj

// ---------------- helpers ----------------
__device__ __forceinline__ float silu_f(float v)  { return v / (1.f + __expf(-v)); }
__device__ __forceinline__ float softplus_f(float v) { return v > 20.f ? v : log1pf(__expf(v)); }

// ---------------- generic NT GEMM: C[M,N] = A[M,K] * B[N,K]^T ----------------
// 64x64 tile, BK=16, 256 threads, 4x4 per thread.
// epi: 0 = none, 1 = softplus(acc + bias[n]), 2 = acc + bias[n]
#define BM 64
#define BN 64
#define BK 16

__global__ __launch_bounds__(256)
void gemm_nt(const float* __restrict__ A, int lda,
             const float* __restrict__ B, int ldb,
             float* __restrict__ C, int ldc,
             int M, int N, int K,
             const float* __restrict__ bias, int epi)
{
    __shared__ float As[BK][BM];
    __shared__ float Bs[BK][BN];

    const int tid = threadIdx.x;
    const int tx = tid & 15;        // 0..15
    const int ty = tid >> 4;        // 0..15
    const int rowBase = blockIdx.y * BM;
    const int colBase = blockIdx.x * BN;

    const int lr = tid >> 2;        // 0..63 (row within tile to load)
    const int lk = (tid & 3) * 4;   // 0,4,8,12 (k offset, float4)

    float acc[4][4];
#pragma unroll
    for (int i = 0; i < 4; i++)
#pragma unroll
        for (int j = 0; j < 4; j++) acc[i][j] = 0.f;

    for (int k0 = 0; k0 < K; k0 += BK) {
        // load A tile (M is always a multiple of 64 here; K multiple of 16)
        {
            const float4 av = *(const float4*)(A + (size_t)(rowBase + lr) * lda + k0 + lk);
            As[lk + 0][lr] = av.x; As[lk + 1][lr] = av.y;
            As[lk + 2][lr] = av.z; As[lk + 3][lr] = av.w;
        }
        // load B tile (guard N)
        {
            const int bn = colBase + lr;
            float4 bv = make_float4(0.f, 0.f, 0.f, 0.f);
            if (bn < N) bv = *(const float4*)(B + (size_t)bn * ldb + k0 + lk);
            Bs[lk + 0][lr] = bv.x; Bs[lk + 1][lr] = bv.y;
            Bs[lk + 2][lr] = bv.z; Bs[lk + 3][lr] = bv.w;
        }
        __syncthreads();

#pragma unroll
        for (int kk = 0; kk < BK; kk++) {
            const float4 a = *(const float4*)&As[kk][ty * 4];
            const float4 b = *(const float4*)&Bs[kk][tx * 4];
            acc[0][0] += a.x * b.x; acc[0][1] += a.x * b.y; acc[0][2] += a.x * b.z; acc[0][3] += a.x * b.w;
            acc[1][0] += a.y * b.x; acc[1][1] += a.y * b.y; acc[1][2] += a.y * b.z; acc[1][3] += a.y * b.w;
            acc[2][0] += a.z * b.x; acc[2][1] += a.z * b.y; acc[2][2] += a.z * b.z; acc[2][3] += a.z * b.w;
            acc[3][0] += a.w * b.x; acc[3][1] += a.w * b.y; acc[3][2] += a.w * b.z; acc[3][3] += a.w * b.w;
        }
        __syncthreads();
    }

#pragma unroll
    for (int i = 0; i < 4; i++) {
        const int row = rowBase + ty * 4 + i;
#pragma unroll
        for (int j = 0; j < 4; j++) {
            const int col = colBase + tx * 4 + j;
            if (col < N) {
                float v = acc[i][j];
                if (epi == 1)      v = softplus_f(v + bias[col]);
                else if (epi == 2) v = v + bias[col];
                C[(size_t)row * ldc + col] = v;
            }
        }
    }
}

// ---------------- causal depthwise conv (width 4) + silu ----------------
__global__ __launch_bounds__(256)
void conv_silu_kernel(const float* __restrict__ xz,
                      const float* __restrict__ conv_w,
                      const float* __restrict__ conv_b,
                      float* __restrict__ xc)
{
    const int idx = blockIdx.x * blockDim.x + threadIdx.x;
    if (idx >= MROWS * DINNER) return;
    const int d = idx % DINNER;
    const int m = idx / DINNER;
    const int t = m % SEQLEN;

    float v = conv_b[d];
#pragma unroll
    for (int k = 0; k < DCONV; k++) {
        const int tt = t + k - (DCONV - 1);
        if (tt >= 0) {
            // x part of xz: row m' = m + (tt - t), column d of first half
            v += conv_w[d * DCONV + k] * xz[(size_t)(m + tt - t) * (2 * DINNER) + d];
        }
    }
    xc[idx] = silu_f(v);
}

// ---------------- selective scan ----------------
// One warp handles 2 (b,d) pairs: lanes 0-15 -> pair0 states, lanes 16-31 -> pair1.
__global__ __launch_bounds__(256)
void scan_kernel(const float* __restrict__ dt,
                 const float* __restrict__ xc,
                 const float* __restrict__ xdbl,
                 const float* __restrict__ A_log,
                 float* __restrict__ y)
{
    const int warp = blockIdx.x * (blockDim.x / 32) + (threadIdx.x >> 5);
    const int lane = threadIdx.x & 31;
    const int half = lane >> 4;            // 0 or 1
    const int n    = lane & 15;            // state index

    const int bd = warp * 2 + half;        // 0 .. 3071
    if (bd >= BATCH * DINNER) return;
    const int b = bd / DINNER;
    const int d = bd % DINNER;

    const float A = -__expf(A_log[d * DSTATE + n]);

    float h = 0.f;
    const size_t rowBase = (size_t)b * SEQLEN;
    for (int t = 0; t < SEQLEN; t++) {
        const size_t m = rowBase + t;
        const float dtv = dt[m * DINNER + d];
        const float xv  = xc[m * DINNER + d];
        const float Bv  = xdbl[m * XDBLW + DTRANK + n];
        const float Cv  = xdbl[m * XDBLW + DTRANK + DSTATE + n];

        h = __expf(dtv * A) * h + (dtv * xv) * Bv;
        float p = h * Cv;
        // reduce over 16 lanes within each half
        p += __shfl_xor_sync(0xffffffffu, p, 8);
        p += __shfl_xor_sync(0xffffffffu, p, 4);
        p += __shfl_xor_sync(0xffffffffu, p, 2);
        p += __shfl_xor_sync(0xffffffffu, p, 1);
        if (n == 0) y[m * DINNER + d] = p;
    }
}

// ---------------- combine: y = (y + xc*D) * silu(z) * silu(q) ----------------
__global__ __launch_bounds__(256)
void combine_kernel(float* __restrict__ y,
                    const float* __restrict__ xc,
                    const float* __restrict__ xz,
                    const float* __restrict__ q,
                    const float* __restrict__ Dp)
{
    const int idx = blockIdx.x * blockDim.x + threadIdx.x;
    if (idx >= MROWS * DINNER) return;
    const int d = idx % DINNER;
    const int m = idx / DINNER;
    const float zv = xz[(size_t)m * (2 * DINNER) + DINNER + d];
    const float qv = q[idx];
    const float v  = (y[idx] + xc[idx] * Dp[d]) * silu_f(zv) * silu_f(qv);
    y[idx] = v;
}

// ---------------- launch ----------------
extern "C" void kernel_launch(void* const* d_in, const int* in_sizes, int n_in,
                              void* d_out, int out_size)
{
    const float* hidden    = (const float*)d_in[0];
    const float* query     = (const float*)d_in[1];
    const float* in_proj_w = (const float*)d_in[2];
    const float* conv_w    = (const float*)d_in[3];
    const float* conv_b    = (const float*)d_in[4];
    const float* x_proj_w  = (const float*)d_in[5];
    const float* dt_proj_w = (const float*)d_in[6];
    const float* dt_proj_b = (const float*)d_in[7];
    const float* A_log     = (const float*)d_in[8];
    const float* Dp        = (const float*)d_in[9];
    const float* query_w   = (const float*)d_in[10];
    const float* query_b   = (const float*)d_in[11];
    const float* out_proj_w= (const float*)d_in[12];
    float* out = (float*)d_out;

    float *xz, *xc, *xdbl, *dt, *y, *q;
    cudaGetSymbolAddress((void**)&xz,   g_xz);
    cudaGetSymbolAddress((void**)&xc,   g_xc);
    cudaGetSymbolAddress((void**)&xdbl, g_xdbl);
    cudaGetSymbolAddress((void**)&dt,   g_dt);
    cudaGetSymbolAddress((void**)&y,    g_y);
    cudaGetSymbolAddress((void**)&q,    g_q);

    const int elemN = MROWS * DINNER;
    const int elemBlocks = (elemN + 255) / 256;

    // 1) xz = hidden @ in_proj_w^T        (4096 x 3072, K=768)
    gemm_nt<<<dim3(2 * DINNER / BN, MROWS / BM), 256>>>(
        hidden, DMODEL, in_proj_w, DMODEL, xz, 2 * DINNER,
        MROWS, 2 * DINNER, DMODEL, nullptr, 0);

    // 2) causal conv + silu -> xc
    conv_silu_kernel<<<elemBlocks, 256>>>(xz, conv_w, conv_b, xc);

    // 3) x_dbl = xc @ x_proj_w^T          (4096 x 80, K=1536)
    gemm_nt<<<dim3((XDBLW + BN - 1) / BN, MROWS / BM), 256>>>(
        xc, DINNER, x_proj_w, DINNER, xdbl, XDBLW,
        MROWS, XDBLW, DINNER, nullptr, 0);

    // 4) dt = softplus(x_dbl[:, :48] @ dt_proj_w^T + b)   (4096 x 1536, K=48)
    gemm_nt<<<dim3(DINNER / BN, MROWS / BM), 256>>>(
        xdbl, XDBLW, dt_proj_w, DTRANK, dt, DINNER,
        MROWS, DINNER, DTRANK, dt_proj_b, 1);

    // 5) q = query @ query_w^T + query_b  (4096 x 1536, K=768)
    gemm_nt<<<dim3(DINNER / BN, MROWS / BM), 256>>>(
        query, DMODEL, query_w, DMODEL, q, DINNER,
        MROWS, DINNER, DMODEL, query_b, 2);

    // 6) selective scan -> y
    scan_kernel<<<(BATCH * DINNER / 2 + 7) / 8, 256>>>(dt, xc, xdbl, A_log, y);

    // 7) combine gates
    combine_kernel<<<elemBlocks, 256>>>(y, xc, xz, q, Dp);

    // 8) out = y @ out_proj_w^T           (4096 x 768, K=1536)
    gemm_nt<<<dim3(DMODEL / BN, MROWS / BM), 256>>>(
        y, DINNER, out_proj_w, DINNER, out, DMODEL,
        MROWS, DMODEL, DINNER, nullptr, 0);
}

// round 2
// speedup vs baseline: 1.1950x; 1.1950x over previous
#include <cuda_runtime.h>
#include <cuda_bf16.h>
#include <math.h>

// ---------------- problem constants ----------------
#define BATCH   2
#define SEQLEN  2048
#define DMODEL  768
#define DINNER  1536
#define DSTATE  16
#define DCONV   4
#define DTRANK  48
#define XDBLW   (DTRANK + 2*DSTATE)   // 80
#define MROWS   (BATCH*SEQLEN)        // 4096
#define NPAIRS  (BATCH*DINNER)        // 3072
#define NCH     16                    // chunks per sequence
#define CHT     (SEQLEN/NCH)          // 128 steps per chunk

// ---------------- scratch (no allocs allowed) ----------------
__device__ float g_xz   [(size_t)MROWS * 2*DINNER];
__device__ float g_xc   [(size_t)MROWS * DINNER];
__device__ float g_xdbl [(size_t)MROWS * XDBLW];
__device__ float g_dt   [(size_t)MROWS * DINNER];
__device__ float g_y    [(size_t)MROWS * DINNER];
__device__ float g_q    [(size_t)MROWS * DINNER];
__device__ float g_aprod[(size_t)NPAIRS * NCH * DSTATE];  // 3 MB
__device__ float g_hloc [(size_t)NPAIRS * NCH * DSTATE];
__device__ float g_h0   [(size_t)NPAIRS * NCH * DSTATE];

// ---------------- helpers ----------------
__device__ __forceinline__ float silu_f(float v)  { return v / (1.f + __expf(-v)); }
__device__ __forceinline__ float softplus_f(float v) { return v > 20.f ? v : log1pf(__expf(v)); }

// ---------------- generic NT GEMM: C[M,N] = A[M,K] * B[N,K]^T ----------------
#define BM 64
#define BN 64
#define BK 16

__global__ __launch_bounds__(256)
void gemm_nt(const float* __restrict__ A, int lda,
             const float* __restrict__ B, int ldb,
             float* __restrict__ C, int ldc,
             int M, int N, int K,
             const float* __restrict__ bias, int epi)
{
    __shared__ float As[BK][BM];
    __shared__ float Bs[BK][BN];

    const int tid = threadIdx.x;
    const int tx = tid & 15;
    const int ty = tid >> 4;
    const int rowBase = blockIdx.y * BM;
    const int colBase = blockIdx.x * BN;

    const int lr = tid >> 2;
    const int lk = (tid & 3) * 4;

    float acc[4][4];
#pragma unroll
    for (int i = 0; i < 4; i++)
#pragma unroll
        for (int j = 0; j < 4; j++) acc[i][j] = 0.f;

    for (int k0 = 0; k0 < K; k0 += BK) {
        {
            const float4 av = *(const float4*)(A + (size_t)(rowBase + lr) * lda + k0 + lk);
            As[lk + 0][lr] = av.x; As[lk + 1][lr] = av.y;
            As[lk + 2][lr] = av.z; As[lk + 3][lr] = av.w;
        }
        {
            const int bn = colBase + lr;
            float4 bv = make_float4(0.f, 0.f, 0.f, 0.f);
            if (bn < N) bv = *(const float4*)(B + (size_t)bn * ldb + k0 + lk);
            Bs[lk + 0][lr] = bv.x; Bs[lk + 1][lr] = bv.y;
            Bs[lk + 2][lr] = bv.z; Bs[lk + 3][lr] = bv.w;
        }
        __syncthreads();

#pragma unroll
        for (int kk = 0; kk < BK; kk++) {
            const float4 a = *(const float4*)&As[kk][ty * 4];
            const float4 b = *(const float4*)&Bs[kk][tx * 4];
            acc[0][0] += a.x * b.x; acc[0][1] += a.x * b.y; acc[0][2] += a.x * b.z; acc[0][3] += a.x * b.w;
            acc[1][0] += a.y * b.x; acc[1][1] += a.y * b.y; acc[1][2] += a.y * b.z; acc[1][3] += a.y * b.w;
            acc[2][0] += a.z * b.x; acc[2][1] += a.z * b.y; acc[2][2] += a.z * b.z; acc[2][3] += a.z * b.w;
            acc[3][0] += a.w * b.x; acc[3][1] += a.w * b.y; acc[3][2] += a.w * b.z; acc[3][3] += a.w * b.w;
        }
        __syncthreads();
    }

#pragma unroll
    for (int i = 0; i < 4; i++) {
        const int row = rowBase + ty * 4 + i;
#pragma unroll
        for (int j = 0; j < 4; j++) {
            const int col = colBase + tx * 4 + j;
            if (col < N) {
                float v = acc[i][j];
                if (epi == 1)      v = softplus_f(v + bias[col]);
                else if (epi == 2) v = v + bias[col];
                C[(size_t)row * ldc + col] = v;
            }
        }
    }
}

// ---------------- causal depthwise conv (width 4) + silu ----------------
__global__ __launch_bounds__(256)
void conv_silu_kernel(const float* __restrict__ xz,
                      const float* __restrict__ conv_w,
                      const float* __restrict__ conv_b,
                      float* __restrict__ xc)
{
    const int idx = blockIdx.x * blockDim.x + threadIdx.x;
    if (idx >= MROWS * DINNER) return;
    const int d = idx % DINNER;
    const int m = idx / DINNER;
    const int t = m % SEQLEN;

    float v = conv_b[d];
#pragma unroll
    for (int k = 0; k < DCONV; k++) {
        const int tt = t + k - (DCONV - 1);
        if (tt >= 0)
            v += conv_w[d * DCONV + k] * xz[(size_t)(m + tt - t) * (2 * DINNER) + d];
    }
    xc[idx] = silu_f(v);
}

// ---------------- chunked selective scan ----------------
// warp layout: lanes 0-15 -> pair (pp*2), lanes 16-31 -> pair (pp*2+1); lane&15 = state n
// warp id -> (chunk c = w & 15, pair-pair pp = w >> 4)

__global__ __launch_bounds__(256)
void scan_phase1(const float* __restrict__ dt,
                 const float* __restrict__ xc,
                 const float* __restrict__ xdbl,
                 const float* __restrict__ A_log,
                 float* __restrict__ aprod_g,
                 float* __restrict__ hloc_g)
{
    const int warp = blockIdx.x * (blockDim.x >> 5) + (threadIdx.x >> 5);
    const int lane = threadIdx.x & 31;
    const int half = lane >> 4;
    const int n    = lane & 15;
    const int c    = warp & (NCH - 1);
    const int pp   = warp >> 4;
    const int bd   = pp * 2 + half;
    if (bd >= NPAIRS) return;
    const int b = bd / DINNER;
    const int d = bd % DINNER;

    const float A = -__expf(A_log[d * DSTATE + n]);

    float ap = 1.f, hl = 0.f;
    const size_t m0 = (size_t)b * SEQLEN + c * CHT;
#pragma unroll 4
    for (int t = 0; t < CHT; t++) {
        const size_t m = m0 + t;
        const float dtv = dt[m * DINNER + d];
        const float xv  = xc[m * DINNER + d];
        const float Bv  = xdbl[m * XDBLW + DTRANK + n];
        const float a   = __expf(dtv * A);
        hl = a * hl + (dtv * xv) * Bv;
        ap *= a;
    }
    const size_t o = ((size_t)bd * NCH + c) * DSTATE + n;
    aprod_g[o] = ap;
    hloc_g[o]  = hl;
}

__global__ __launch_bounds__(256)
void scan_phase2(const float* __restrict__ aprod_g,
                 const float* __restrict__ hloc_g,
                 float* __restrict__ h0_g)
{
    const int idx = blockIdx.x * blockDim.x + threadIdx.x;
    const int bd = idx >> 4;
    const int n  = idx & 15;
    if (bd >= NPAIRS) return;

    float h = 0.f;
#pragma unroll
    for (int c = 0; c < NCH; c++) {
        const size_t o = ((size_t)bd * NCH + c) * DSTATE + n;
        h0_g[o] = h;
        h = aprod_g[o] * h + hloc_g[o];
    }
}

__global__ __launch_bounds__(256)
void scan_phase3(const float* __restrict__ dt,
                 const float* __restrict__ xc,
                 const float* __restrict__ xdbl,
                 const float* __restrict__ A_log,
                 const float* __restrict__ h0_g,
                 float* __restrict__ y)
{
    const int warp = blockIdx.x * (blockDim.x >> 5) + (threadIdx.x >> 5);
    const int lane = threadIdx.x & 31;
    const int half = lane >> 4;
    const int n    = lane & 15;
    const int c    = warp & (NCH - 1);
    const int pp   = warp >> 4;
    const int bd   = pp * 2 + half;
    if (bd >= NPAIRS) return;
    const int b = bd / DINNER;
    const int d = bd % DINNER;

    const float A = -__expf(A_log[d * DSTATE + n]);
    float h = h0_g[((size_t)bd * NCH + c) * DSTATE + n];

    const size_t m0 = (size_t)b * SEQLEN + c * CHT;
#pragma unroll 2
    for (int t = 0; t < CHT; t++) {
        const size_t m = m0 + t;
        const float dtv = dt[m * DINNER + d];
        const float xv  = xc[m * DINNER + d];
        const float Bv  = xdbl[m * XDBLW + DTRANK + n];
        const float Cv  = xdbl[m * XDBLW + DTRANK + DSTATE + n];
        const float a   = __expf(dtv * A);
        h = a * h + (dtv * xv) * Bv;
        float p = h * Cv;
        p += __shfl_xor_sync(0xffffffffu, p, 8);
        p += __shfl_xor_sync(0xffffffffu, p, 4);
        p += __shfl_xor_sync(0xffffffffu, p, 2);
        p += __shfl_xor_sync(0xffffffffu, p, 1);
        if (n == 0) y[m * DINNER + d] = p;
    }
}

// ---------------- combine: y = (y + xc*D) * silu(z) * silu(q) ----------------
__global__ __launch_bounds__(256)
void combine_kernel(float* __restrict__ y,
                    const float* __restrict__ xc,
                    const float* __restrict__ xz,
                    const float* __restrict__ q,
                    const float* __restrict__ Dp)
{
    const int idx = blockIdx.x * blockDim.x + threadIdx.x;
    if (idx >= MROWS * DINNER) return;
    const int d = idx % DINNER;
    const int m = idx / DINNER;
    const float zv = xz[(size_t)m * (2 * DINNER) + DINNER + d];
    const float qv = q[idx];
    const float v  = (y[idx] + xc[idx] * Dp[d]) * silu_f(zv) * silu_f(qv);
    y[idx] = v;
}

// ---------------- launch ----------------
extern "C" void kernel_launch(void* const* d_in, const int* in_sizes, int n_in,
                              void* d_out, int out_size)
{
    const float* hidden    = (const float*)d_in[0];
    const float* query     = (const float*)d_in[1];
    const float* in_proj_w = (const float*)d_in[2];
    const float* conv_w    = (const float*)d_in[3];
    const float* conv_b    = (const float*)d_in[4];
    const float* x_proj_w  = (const float*)d_in[5];
    const float* dt_proj_w = (const float*)d_in[6];
    const float* dt_proj_b = (const float*)d_in[7];
    const float* A_log     = (const float*)d_in[8];
    const float* Dp        = (const float*)d_in[9];
    const float* query_w   = (const float*)d_in[10];
    const float* query_b   = (const float*)d_in[11];
    const float* out_proj_w= (const float*)d_in[12];
    float* out = (float*)d_out;

    float *xz, *xc, *xdbl, *dt, *y, *q, *aprod, *hloc, *h0;
    cudaGetSymbolAddress((void**)&xz,    g_xz);
    cudaGetSymbolAddress((void**)&xc,    g_xc);
    cudaGetSymbolAddress((void**)&xdbl,  g_xdbl);
    cudaGetSymbolAddress((void**)&dt,    g_dt);
    cudaGetSymbolAddress((void**)&y,     g_y);
    cudaGetSymbolAddress((void**)&q,     g_q);
    cudaGetSymbolAddress((void**)&aprod, g_aprod);
    cudaGetSymbolAddress((void**)&hloc,  g_hloc);
    cudaGetSymbolAddress((void**)&h0,    g_h0);

    const int elemN = MROWS * DINNER;
    const int elemBlocks = (elemN + 255) / 256;

    // 1) xz = hidden @ in_proj_w^T
    gemm_nt<<<dim3(2 * DINNER / BN, MROWS / BM), 256>>>(
        hidden, DMODEL, in_proj_w, DMODEL, xz, 2 * DINNER,
        MROWS, 2 * DINNER, DMODEL, nullptr, 0);

    // 2) causal conv + silu
    conv_silu_kernel<<<elemBlocks, 256>>>(xz, conv_w, conv_b, xc);

    // 3) x_dbl = xc @ x_proj_w^T
    gemm_nt<<<dim3((XDBLW + BN - 1) / BN, MROWS / BM), 256>>>(
        xc, DINNER, x_proj_w, DINNER, xdbl, XDBLW,
        MROWS, XDBLW, DINNER, nullptr, 0);

    // 4) dt = softplus(x_dbl[:, :48] @ dt_proj_w^T + b)
    gemm_nt<<<dim3(DINNER / BN, MROWS / BM), 256>>>(
        xdbl, XDBLW, dt_proj_w, DTRANK, dt, DINNER,
        MROWS, DINNER, DTRANK, dt_proj_b, 1);

    // 5) q = query @ query_w^T + query_b
    gemm_nt<<<dim3(DINNER / BN, MROWS / BM), 256>>>(
        query, DMODEL, query_w, DMODEL, q, DINNER,
        MROWS, DINNER, DMODEL, query_b, 2);

    // 6) chunked selective scan
    {
        const int warpsTotal = (NPAIRS / 2) * NCH;       // 24576
        scan_phase1<<<warpsTotal / 8, 256>>>(dt, xc, xdbl, A_log, aprod, hloc);
        scan_phase2<<<(NPAIRS * DSTATE) / 256, 256>>>(aprod, hloc, h0);
        scan_phase3<<<warpsTotal / 8, 256>>>(dt, xc, xdbl, A_log, h0, y);
    }

    // 7) combine gates
    combine_kernel<<<elemBlocks, 256>>>(y, xc, xz, q, Dp);

    // 8) out = y @ out_proj_w^T
    gemm_nt<<<dim3(DMODEL / BN, MROWS / BM), 256>>>(
        y, DINNER, out_proj_w, DINNER, out, DMODEL,
        MROWS, DMODEL, DINNER, nullptr, 0);
}

// round 4
// speedup vs baseline: 2.0809x; 1.7413x over previous
#include <cuda_runtime.h>
#include <cuda_bf16.h>
#include <math.h>
#include <stdint.h>

// ---------------- problem constants ----------------
#define BATCH   2
#define SEQLEN  2048
#define DMODEL  768
#define DINNER  1536
#define DSTATE  16
#define DCONV   4
#define DTRANK  48
#define XDBLW   (DTRANK + 2*DSTATE)   // 80
#define MROWS   (BATCH*SEQLEN)        // 4096
#define NPAIRS  (BATCH*DINNER)        // 3072
#define NCH     16
#define CHT     (SEQLEN/NCH)          // 128

// ---------------- scratch ----------------
__device__ float g_xz   [(size_t)MROWS * 2*DINNER];
__device__ float g_xc   [(size_t)MROWS * DINNER];
__device__ float g_xdbl [(size_t)MROWS * XDBLW];
__device__ float g_dt   [(size_t)MROWS * DINNER];
__device__ float g_y    [(size_t)MROWS * DINNER];
__device__ float g_q    [(size_t)MROWS * DINNER];
__device__ float g_aprod[(size_t)NPAIRS * NCH * DSTATE];
__device__ float g_hloc [(size_t)NPAIRS * NCH * DSTATE];
__device__ float g_h0   [(size_t)NPAIRS * NCH * DSTATE];

// ---------------- helpers ----------------
__device__ __forceinline__ float silu_f(float v)  { return v / (1.f + __expf(-v)); }
__device__ __forceinline__ float softplus_f(float v) { return v > 20.f ? v : log1pf(__expf(v)); }
__device__ __forceinline__ uint32_t f2tf32(float f) {
    uint32_t u; asm("cvt.rna.tf32.f32 %0, %1;" : "=r"(u) : "f"(f)); return u;
}
__device__ __forceinline__ void mma_tf32(float c[4], const uint32_t a[4], const uint32_t b[2]) {
    asm volatile(
        "mma.sync.aligned.m16n8k8.row.col.f32.tf32.tf32.f32 "
        "{%0,%1,%2,%3}, {%4,%5,%6,%7}, {%8,%9}, {%0,%1,%2,%3};\n"
        : "+f"(c[0]), "+f"(c[1]), "+f"(c[2]), "+f"(c[3])
        : "r"(a[0]), "r"(a[1]), "r"(a[2]), "r"(a[3]), "r"(b[0]), "r"(b[1]));
}

// ---------------- TF32 tensor-core GEMM: C[M,N] = A[M,K] * B[N,K]^T ----------------
// Block 128x128, BK=16, 256 threads = 8 warps (2 x 4), warp tile 64x32.
// Requires: M % 128 == 0, K % 16 == 0. N arbitrary (guarded, zero-filled).
// epi: 0 none, 1 softplus(acc+bias[n]), 2 acc+bias[n]
#define TBM 128
#define TBN 128
#define TBK 16
#define SPAD 4

__global__ __launch_bounds__(256)
void gemm_tf32(const float* __restrict__ A, int lda,
               const float* __restrict__ B, int ldb,
               float* __restrict__ C, int ldc,
               int M, int N, int K,
               const float* __restrict__ bias, int epi)
{
    __shared__ float As[TBK][TBM + SPAD];
    __shared__ float Bs[TBK][TBN + SPAD];

    const int tid   = threadIdx.x;
    const int warp  = tid >> 5;
    const int lane  = tid & 31;
    const int warpM = warp >> 2;      // 0..1  (x64 rows)
    const int warpN = warp & 3;       // 0..3  (x32 cols)
    const int gid   = lane >> 2;      // 0..7
    const int tg    = lane & 3;       // 0..3

    const int rowBase = blockIdx.y * TBM;
    const int colBase = blockIdx.x * TBN;

    // global->shared load mapping: each thread loads 8 A floats + 8 B floats per tile
    const int lr = tid >> 1;          // 0..127 (row within tile)
    const int lk = (tid & 1) * 8;     // 0 or 8 (k offset)

    float acc[4][4][4];
#pragma unroll
    for (int mi = 0; mi < 4; mi++)
#pragma unroll
        for (int ni = 0; ni < 4; ni++)
#pragma unroll
            for (int r = 0; r < 4; r++) acc[mi][ni][r] = 0.f;

    // prefetch first tile into registers
    float4 pa0, pa1, pb0, pb1;
    {
        const float* ap = A + (size_t)(rowBase + lr) * lda + lk;
        pa0 = *(const float4*)(ap);
        pa1 = *(const float4*)(ap + 4);
        const int bn = colBase + lr;
        if (bn < N) {
            const float* bp = B + (size_t)bn * ldb + lk;
            pb0 = *(const float4*)(bp);
            pb1 = *(const float4*)(bp + 4);
        } else {
            pb0 = make_float4(0.f,0.f,0.f,0.f);
            pb1 = make_float4(0.f,0.f,0.f,0.f);
        }
    }

    for (int k0 = 0; k0 < K; k0 += TBK) {
        // commit prefetched tile to shared (tf32-rounded)
        As[lk+0][lr] = __uint_as_float(f2tf32(pa0.x));
        As[lk+1][lr] = __uint_as_float(f2tf32(pa0.y));
        As[lk+2][lr] = __uint_as_float(f2tf32(pa0.z));
        As[lk+3][lr] = __uint_as_float(f2tf32(pa0.w));
        As[lk+4][lr] = __uint_as_float(f2tf32(pa1.x));
        As[lk+5][lr] = __uint_as_float(f2tf32(pa1.y));
        As[lk+6][lr] = __uint_as_float(f2tf32(pa1.z));
        As[lk+7][lr] = __uint_as_float(f2tf32(pa1.w));
        Bs[lk+0][lr] = __uint_as_float(f2tf32(pb0.x));
        Bs[lk+1][lr] = __uint_as_float(f2tf32(pb0.y));
        Bs[lk+2][lr] = __uint_as_float(f2tf32(pb0.z));
        Bs[lk+3][lr] = __uint_as_float(f2tf32(pb0.w));
        Bs[lk+4][lr] = __uint_as_float(f2tf32(pb1.x));
        Bs[lk+5][lr] = __uint_as_float(f2tf32(pb1.y));
        Bs[lk+6][lr] = __uint_as_float(f2tf32(pb1.z));
        Bs[lk+7][lr] = __uint_as_float(f2tf32(pb1.w));
        __syncthreads();

        // prefetch next tile
        if (k0 + TBK < K) {
            const float* ap = A + (size_t)(rowBase + lr) * lda + (k0 + TBK) + lk;
            pa0 = *(const float4*)(ap);
            pa1 = *(const float4*)(ap + 4);
            const int bn = colBase + lr;
            if (bn < N) {
                const float* bp = B + (size_t)bn * ldb + (k0 + TBK) + lk;
                pb0 = *(const float4*)(bp);
                pb1 = *(const float4*)(bp + 4);
            } else {
                pb0 = make_float4(0.f,0.f,0.f,0.f);
                pb1 = make_float4(0.f,0.f,0.f,0.f);
            }
        }

        // compute: 2 k-steps of m16n8k8
#pragma unroll
        for (int ks = 0; ks < 2; ks++) {
            const int kb = ks * 8;
            uint32_t afrag[4][4];
#pragma unroll
            for (int mi = 0; mi < 4; mi++) {
                const int m = warpM * 64 + mi * 16;
                afrag[mi][0] = __float_as_uint(As[kb+tg  ][m+gid  ]);
                afrag[mi][1] = __float_as_uint(As[kb+tg  ][m+gid+8]);
                afrag[mi][2] = __float_as_uint(As[kb+tg+4][m+gid  ]);
                afrag[mi][3] = __float_as_uint(As[kb+tg+4][m+gid+8]);
            }
            uint32_t bfrag[4][2];
#pragma unroll
            for (int ni = 0; ni < 4; ni++) {
                const int n = warpN * 32 + ni * 8;
                bfrag[ni][0] = __float_as_uint(Bs[kb+tg  ][n+gid]);
                bfrag[ni][1] = __float_as_uint(Bs[kb+tg+4][n+gid]);
            }
#pragma unroll
            for (int mi = 0; mi < 4; mi++)
#pragma unroll
                for (int ni = 0; ni < 4; ni++)
                    mma_tf32(acc[mi][ni], afrag[mi], bfrag[ni]);
        }
        __syncthreads();
    }

    // epilogue
#pragma unroll
    for (int mi = 0; mi < 4; mi++) {
        const int r0 = rowBase + warpM * 64 + mi * 16 + gid;
#pragma unroll
        for (int ni = 0; ni < 4; ni++) {
            const int c = colBase + warpN * 32 + ni * 8 + 2 * tg;
            if (c < N) {  // N even, c even -> c+1 also < N
                float v0 = acc[mi][ni][0], v1 = acc[mi][ni][1];
                float v2 = acc[mi][ni][2], v3 = acc[mi][ni][3];
                if (epi == 1) {
                    const float b0 = bias[c], b1 = bias[c+1];
                    v0 = softplus_f(v0 + b0); v1 = softplus_f(v1 + b1);
                    v2 = softplus_f(v2 + b0); v3 = softplus_f(v3 + b1);
                } else if (epi == 2) {
                    const float b0 = bias[c], b1 = bias[c+1];
                    v0 += b0; v1 += b1; v2 += b0; v3 += b1;
                }
                *(float2*)(C + (size_t)r0       * ldc + c) = make_float2(v0, v1);
                *(float2*)(C + (size_t)(r0 + 8) * ldc + c) = make_float2(v2, v3);
            }
        }
    }
}

// ---------------- causal depthwise conv (width 4) + silu ----------------
__global__ __launch_bounds__(256)
void conv_silu_kernel(const float* __restrict__ xz,
                      const float* __restrict__ conv_w,
                      const float* __restrict__ conv_b,
                      float* __restrict__ xc)
{
    const int idx = blockIdx.x * blockDim.x + threadIdx.x;
    if (idx >= MROWS * DINNER) return;
    const int d = idx % DINNER;
    const int m = idx / DINNER;
    const int t = m % SEQLEN;

    float v = conv_b[d];
#pragma unroll
    for (int k = 0; k < DCONV; k++) {
        const int tt = t + k - (DCONV - 1);
        if (tt >= 0)
            v += conv_w[d * DCONV + k] * xz[(size_t)(m + tt - t) * (2 * DINNER) + d];
    }
    xc[idx] = silu_f(v);
}

// ---------------- chunked selective scan ----------------
__global__ __launch_bounds__(256)
void scan_phase1(const float* __restrict__ dt,
                 const float* __restrict__ xc,
                 const float* __restrict__ xdbl,
                 const float* __restrict__ A_log,
                 float* __restrict__ aprod_g,
                 float* __restrict__ hloc_g)
{
    const int warp = blockIdx.x * (blockDim.x >> 5) + (threadIdx.x >> 5);
    const int lane = threadIdx.x & 31;
    const int half = lane >> 4;
    const int n    = lane & 15;
    const int c    = warp & (NCH - 1);
    const int pp   = warp >> 4;
    const int bd   = pp * 2 + half;
    if (bd >= NPAIRS) return;
    const int b = bd / DINNER;
    const int d = bd % DINNER;

    const float A = -__expf(A_log[d * DSTATE + n]);

    float ap = 1.f, hl = 0.f;
    const size_t m0 = (size_t)b * SEQLEN + c * CHT;
#pragma unroll 4
    for (int t = 0; t < CHT; t++) {
        const size_t m = m0 + t;
        const float dtv = dt[m * DINNER + d];
        const float xv  = xc[m * DINNER + d];
        const float Bv  = xdbl[m * XDBLW + DTRANK + n];
        const float a   = __expf(dtv * A);
        hl = a * hl + (dtv * xv) * Bv;
        ap *= a;
    }
    const size_t o = ((size_t)bd * NCH + c) * DSTATE + n;
    aprod_g[o] = ap;
    hloc_g[o]  = hl;
}

__global__ __launch_bounds__(256)
void scan_phase2(const float* __restrict__ aprod_g,
                 const float* __restrict__ hloc_g,
                 float* __restrict__ h0_g)
{
    const int idx = blockIdx.x * blockDim.x + threadIdx.x;
    const int bd = idx >> 4;
    const int n  = idx & 15;
    if (bd >= NPAIRS) return;

    float h = 0.f;
#pragma unroll
    for (int c = 0; c < NCH; c++) {
        const size_t o = ((size_t)bd * NCH + c) * DSTATE + n;
        h0_g[o] = h;
        h = aprod_g[o] * h + hloc_g[o];
    }
}

__global__ __launch_bounds__(256)
void scan_phase3(const float* __restrict__ dt,
                 const float* __restrict__ xc,
                 const float* __restrict__ xdbl,
                 const float* __restrict__ A_log,
                 const float* __restrict__ h0_g,
                 float* __restrict__ y)
{
    const int warp = blockIdx.x * (blockDim.x >> 5) + (threadIdx.x >> 5);
    const int lane = threadIdx.x & 31;
    const int half = lane >> 4;
    const int n    = lane & 15;
    const int c    = warp & (NCH - 1);
    const int pp   = warp >> 4;
    const int bd   = pp * 2 + half;
    if (bd >= NPAIRS) return;
    const int b = bd / DINNER;
    const int d = bd % DINNER;

    const float A = -__expf(A_log[d * DSTATE + n]);
    float h = h0_g[((size_t)bd * NCH + c) * DSTATE + n];

    const size_t m0 = (size_t)b * SEQLEN + c * CHT;
#pragma unroll 2
    for (int t = 0; t < CHT; t++) {
        const size_t m = m0 + t;
        const float dtv = dt[m * DINNER + d];
        const float xv  = xc[m * DINNER + d];
        const float Bv  = xdbl[m * XDBLW + DTRANK + n];
        const float Cv  = xdbl[m * XDBLW + DTRANK + DSTATE + n];
        const float a   = __expf(dtv * A);
        h = a * h + (dtv * xv) * Bv;
        float p = h * Cv;
        p += __shfl_xor_sync(0xffffffffu, p, 8);
        p += __shfl_xor_sync(0xffffffffu, p, 4);
        p += __shfl_xor_sync(0xffffffffu, p, 2);
        p += __shfl_xor_sync(0xffffffffu, p, 1);
        if (n == 0) y[m * DINNER + d] = p;
    }
}

// ---------------- combine ----------------
__global__ __launch_bounds__(256)
void combine_kernel(float* __restrict__ y,
                    const float* __restrict__ xc,
                    const float* __restrict__ xz,
                    const float* __restrict__ q,
                    const float* __restrict__ Dp)
{
    const int idx = blockIdx.x * blockDim.x + threadIdx.x;
    if (idx >= MROWS * DINNER) return;
    const int d = idx % DINNER;
    const int m = idx / DINNER;
    const float zv = xz[(size_t)m * (2 * DINNER) + DINNER + d];
    const float qv = q[idx];
    const float v  = (y[idx] + xc[idx] * Dp[d]) * silu_f(zv) * silu_f(qv);
    y[idx] = v;
}

// ---------------- launch ----------------
extern "C" void kernel_launch(void* const* d_in, const int* in_sizes, int n_in,
                              void* d_out, int out_size)
{
    const float* hidden    = (const float*)d_in[0];
    const float* query     = (const float*)d_in[1];
    const float* in_proj_w = (const float*)d_in[2];
    const float* conv_w    = (const float*)d_in[3];
    const float* conv_b    = (const float*)d_in[4];
    const float* x_proj_w  = (const float*)d_in[5];
    const float* dt_proj_w = (const float*)d_in[6];
    const float* dt_proj_b = (const float*)d_in[7];
    const float* A_log     = (const float*)d_in[8];
    const float* Dp        = (const float*)d_in[9];
    const float* query_w   = (const float*)d_in[10];
    const float* query_b   = (const float*)d_in[11];
    const float* out_proj_w= (const float*)d_in[12];
    float* out = (float*)d_out;

    float *xz, *xc, *xdbl, *dt, *y, *q, *aprod, *hloc, *h0;
    cudaGetSymbolAddress((void**)&xz,    g_xz);
    cudaGetSymbolAddress((void**)&xc,    g_xc);
    cudaGetSymbolAddress((void**)&xdbl,  g_xdbl);
    cudaGetSymbolAddress((void**)&dt,    g_dt);
    cudaGetSymbolAddress((void**)&y,     g_y);
    cudaGetSymbolAddress((void**)&q,     g_q);
    cudaGetSymbolAddress((void**)&aprod, g_aprod);
    cudaGetSymbolAddress((void**)&hloc,  g_hloc);
    cudaGetSymbolAddress((void**)&h0,    g_h0);

    const int elemN = MROWS * DINNER;
    const int elemBlocks = (elemN + 255) / 256;

    // 1) xz = hidden @ in_proj_w^T        (4096 x 3072, K=768)
    gemm_tf32<<<dim3(2 * DINNER / TBN, MROWS / TBM), 256>>>(
        hidden, DMODEL, in_proj_w, DMODEL, xz, 2 * DINNER,
        MROWS, 2 * DINNER, DMODEL, nullptr, 0);

    // 2) causal conv + silu
    conv_silu_kernel<<<elemBlocks, 256>>>(xz, conv_w, conv_b, xc);

    // 3) x_dbl = xc @ x_proj_w^T          (4096 x 80, K=1536)
    gemm_tf32<<<dim3(1, MROWS / TBM), 256>>>(
        xc, DINNER, x_proj_w, DINNER, xdbl, XDBLW,
        MROWS, XDBLW, DINNER, nullptr, 0);

    // 4) dt = softplus(x_dbl[:, :48] @ dt_proj_w^T + b)   (4096 x 1536, K=48)
    gemm_tf32<<<dim3(DINNER / TBN, MROWS / TBM), 256>>>(
        xdbl, XDBLW, dt_proj_w, DTRANK, dt, DINNER,
        MROWS, DINNER, DTRANK, dt_proj_b, 1);

    // 5) q = query @ query_w^T + query_b  (4096 x 1536, K=768)
    gemm_tf32<<<dim3(DINNER / TBN, MROWS / TBM), 256>>>(
        query, DMODEL, query_w, DMODEL, q, DINNER,
        MROWS, DINNER, DMODEL, query_b, 2);

    // 6) chunked selective scan
    {
        const int warpsTotal = (NPAIRS / 2) * NCH;       // 24576
        scan_phase1<<<warpsTotal / 8, 256>>>(dt, xc, xdbl, A_log, aprod, hloc);
        scan_phase2<<<(NPAIRS * DSTATE) / 256, 256>>>(aprod, hloc, h0);
        scan_phase3<<<warpsTotal / 8, 256>>>(dt, xc, xdbl, A_log, h0, y);
    }

    // 7) combine gates
    combine_kernel<<<elemBlocks, 256>>>(y, xc, xz, q, Dp);

    // 8) out = y @ out_proj_w^T           (4096 x 768, K=1536)
    gemm_tf32<<<dim3(DMODEL / TBN, MROWS / TBM), 256>>>(
        y, DINNER, out_proj_w, DINNER, out, DMODEL,
        MROWS, DMODEL, DINNER, nullptr, 0);
}

// round 5
// speedup vs baseline: 3.2061x; 1.5407x over previous
#include <cuda_runtime.h>
#include <cuda_bf16.h>
#include <math.h>
#include <stdint.h>

// ---------------- problem constants ----------------
#define BATCH   2
#define SEQLEN  2048
#define DMODEL  768
#define DINNER  1536
#define DSTATE  16
#define DCONV   4
#define DTRANK  48
#define XDBLW   (DTRANK + 2*DSTATE)   // 80
#define MROWS   (BATCH*SEQLEN)        // 4096
#define NPAIRS  (BATCH*DINNER)        // 3072
#define NCH     16
#define CHT     (SEQLEN/NCH)          // 128
#define SPLITK  4
#define XPSTRIDE ((size_t)MROWS * XDBLW)

// ---------------- scratch ----------------
__device__ float g_xz   [(size_t)MROWS * 2*DINNER];
__device__ float g_xc   [(size_t)MROWS * DINNER];
__device__ float g_xdbl [(size_t)MROWS * XDBLW];
__device__ float g_xp   [(size_t)SPLITK * MROWS * XDBLW];
__device__ float g_dt   [(size_t)MROWS * DINNER];
__device__ float g_y    [(size_t)MROWS * DINNER];
__device__ float g_q    [(size_t)MROWS * DINNER];
__device__ float g_aprod[(size_t)NPAIRS * NCH * DSTATE];
__device__ float g_hloc [(size_t)NPAIRS * NCH * DSTATE];
__device__ float g_h0   [(size_t)NPAIRS * NCH * DSTATE];

// ---------------- helpers ----------------
__device__ __forceinline__ float silu_f(float v)  { return v / (1.f + __expf(-v)); }
__device__ __forceinline__ float softplus_f(float v) { return v > 20.f ? v : log1pf(__expf(v)); }
__device__ __forceinline__ uint32_t f2tf32(float f) {
    uint32_t u; asm("cvt.rna.tf32.f32 %0, %1;" : "=r"(u) : "f"(f)); return u;
}
__device__ __forceinline__ void mma_tf32(float c[4], const uint32_t a[4], const uint32_t b[2]) {
    asm volatile(
        "mma.sync.aligned.m16n8k8.row.col.f32.tf32.tf32.f32 "
        "{%0,%1,%2,%3}, {%4,%5,%6,%7}, {%8,%9}, {%0,%1,%2,%3};\n"
        : "+f"(c[0]), "+f"(c[1]), "+f"(c[2]), "+f"(c[3])
        : "r"(a[0]), "r"(a[1]), "r"(a[2]), "r"(a[3]), "r"(b[0]), "r"(b[1]));
}
__device__ __forceinline__ int swz(int c) { return (c ^ (c >> 2)) & 31; }

// ---------------- TF32 tensor-core GEMM: C[M,N] = A[M,K] * B[N,K]^T ----------------
// Block 128x128, BK=16, 256 thr = 8 warps (2M x 4N), warp tile 64x32.
// Smem holds tiles in per-lane MMA fragment layout (swizzled): compute loop
// reads 4xLDS.128 (A) + 4xLDS.64 (B) per 8-k step. Double buffered, 1 sync/tile.
// Requires M % 128 == 0, K % (16*gridDim.z) == 0. N guarded.
// epi: 0 none, 1 softplus(acc+bias[n]), 2 acc+bias[n]
#define TBM 128
#define TBN 128
#define TBK 16

__global__ __launch_bounds__(256)
void gemm_tf32(const float* __restrict__ A, int lda,
               const float* __restrict__ B, int ldb,
               float* __restrict__ C, int ldc,
               int M, int N, int K,
               const float* __restrict__ bias, int epi,
               size_t splitStride)
{
    // Af: [buf][ks][mi'(8)][128 floats = 32 chunks x 4 frag]
    // Bf: [buf][ks][ni'(16)][64 floats = 32 chunks x 2 frag]
    __shared__ float Af[2][2][8][128];
    __shared__ float Bf[2][2][16][64];

    const int tid  = threadIdx.x;
    const int warp = tid >> 5, lane = tid & 31;
    const int warpM = warp >> 2, warpN = warp & 3;

    const int rowBase = blockIdx.y * TBM;
    const int colBase = blockIdx.x * TBN;

    const int Ks = K / gridDim.z;
    A += (size_t)blockIdx.z * Ks;
    B += (size_t)blockIdx.z * Ks;
    C += (size_t)blockIdx.z * splitStride;

    const int lr  = tid >> 1;        // 0..127 tile row
    const int lks = tid & 1;         // which 8-k group
    const int lk  = lks * 8;

    const int wmi  = lr >> 4;        // A writer: m16-tile id
    const int wsel = (lr >> 3) & 1;  // row<8 or >=8 within m16 tile
    const int wgid = lr & 7;
    const int wni  = lr >> 3;        // B writer: n8-tile id
    const int wbg  = lr & 7;

    float acc[4][4][4];
#pragma unroll
    for (int mi = 0; mi < 4; mi++)
#pragma unroll
        for (int ni = 0; ni < 4; ni++)
#pragma unroll
            for (int r = 0; r < 4; r++) acc[mi][ni][r] = 0.f;

    float4 pa0, pa1, pb0, pb1;
    {
        const float* ap = A + (size_t)(rowBase + lr) * lda + lk;
        pa0 = *(const float4*)(ap);
        pa1 = *(const float4*)(ap + 4);
        const int bn = colBase + lr;
        if (bn < N) {
            const float* bp = B + (size_t)bn * ldb + lk;
            pb0 = *(const float4*)(bp);
            pb1 = *(const float4*)(bp + 4);
        } else {
            pb0 = make_float4(0.f,0.f,0.f,0.f);
            pb1 = make_float4(0.f,0.f,0.f,0.f);
        }
    }

    const int ntiles = Ks / TBK;
    for (int t = 0; t < ntiles; t++) {
        const int buf = t & 1;
        // ---- commit prefetched tile into fragment-layout smem ----
        {
            const float ea[8] = {pa0.x,pa0.y,pa0.z,pa0.w,pa1.x,pa1.y,pa1.z,pa1.w};
#pragma unroll
            for (int j = 0; j < 8; j++) {
                const int ch = swz(wgid * 4 + (j & 3));
                Af[buf][lks][wmi][ch * 4 + (j >> 2) * 2 + wsel] =
                    __uint_as_float(f2tf32(ea[j]));
            }
            const float eb[8] = {pb0.x,pb0.y,pb0.z,pb0.w,pb1.x,pb1.y,pb1.z,pb1.w};
#pragma unroll
            for (int j = 0; j < 4; j++) {
                const int ch = swz(wbg * 4 + j);
                Bf[buf][lks][wni][ch * 2 + 0] = __uint_as_float(f2tf32(eb[j]));
                Bf[buf][lks][wni][ch * 2 + 1] = __uint_as_float(f2tf32(eb[j + 4]));
            }
        }
        __syncthreads();

        // ---- prefetch next tile ----
        if (t + 1 < ntiles) {
            const int k0 = (t + 1) * TBK;
            const float* apn = A + (size_t)(rowBase + lr) * lda + k0 + lk;
            pa0 = *(const float4*)(apn);
            pa1 = *(const float4*)(apn + 4);
            const int bn = colBase + lr;
            if (bn < N) {
                const float* bpn = B + (size_t)bn * ldb + k0 + lk;
                pb0 = *(const float4*)(bpn);
                pb1 = *(const float4*)(bpn + 4);
            } else {
                pb0 = make_float4(0.f,0.f,0.f,0.f);
                pb1 = make_float4(0.f,0.f,0.f,0.f);
            }
        }

        // ---- compute from smem (vectorized fragment loads) ----
#pragma unroll
        for (int ks = 0; ks < 2; ks++) {
            uint32_t af[4][4], bfr[4][2];
#pragma unroll
            for (int mi = 0; mi < 4; mi++) {
                const float4 v = *(const float4*)&Af[buf][ks][warpM*4 + mi][swz(lane)*4];
                af[mi][0] = __float_as_uint(v.x); af[mi][1] = __float_as_uint(v.y);
                af[mi][2] = __float_as_uint(v.z); af[mi][3] = __float_as_uint(v.w);
            }
#pragma unroll
            for (int ni = 0; ni < 4; ni++) {
                const float2 w = *(const float2*)&Bf[buf][ks][warpN*4 + ni][swz(lane)*2];
                bfr[ni][0] = __float_as_uint(w.x); bfr[ni][1] = __float_as_uint(w.y);
            }
#pragma unroll
            for (int mi = 0; mi < 4; mi++)
#pragma unroll
                for (int ni = 0; ni < 4; ni++)
                    mma_tf32(acc[mi][ni], af[mi], bfr[ni]);
        }
    }

    // ---- epilogue ----
    const int gid = lane >> 2, tg = lane & 3;
#pragma unroll
    for (int mi = 0; mi < 4; mi++) {
        const int r0 = rowBase + warpM * 64 + mi * 16 + gid;
#pragma unroll
        for (int ni = 0; ni < 4; ni++) {
            const int c = colBase + warpN * 32 + ni * 8 + 2 * tg;
            if (c < N) {
                float v0 = acc[mi][ni][0], v1 = acc[mi][ni][1];
                float v2 = acc[mi][ni][2], v3 = acc[mi][ni][3];
                if (epi == 1) {
                    const float b0 = bias[c], b1 = bias[c+1];
                    v0 = softplus_f(v0 + b0); v1 = softplus_f(v1 + b1);
                    v2 = softplus_f(v2 + b0); v3 = softplus_f(v3 + b1);
                } else if (epi == 2) {
                    const float b0 = bias[c], b1 = bias[c+1];
                    v0 += b0; v1 += b1; v2 += b0; v3 += b1;
                }
                *(float2*)(C + (size_t)r0       * ldc + c) = make_float2(v0, v1);
                *(float2*)(C + (size_t)(r0 + 8) * ldc + c) = make_float2(v2, v3);
            }
        }
    }
}

// ---------------- split-K reduction for x_proj ----------------
__global__ __launch_bounds__(256)
void reduce_xp(const float* __restrict__ part, float* __restrict__ xdbl)
{
    const int i = blockIdx.x * blockDim.x + threadIdx.x;
    if (i < (int)(MROWS * XDBLW)) {
        float s = part[i];
#pragma unroll
        for (int k = 1; k < SPLITK; k++) s += part[(size_t)k * XPSTRIDE + i];
        xdbl[i] = s;
    }
}

// ---------------- causal depthwise conv (width 4) + silu ----------------
__global__ __launch_bounds__(256)
void conv_silu_kernel(const float* __restrict__ xz,
                      const float* __restrict__ conv_w,
                      const float* __restrict__ conv_b,
                      float* __restrict__ xc)
{
    const int idx = blockIdx.x * blockDim.x + threadIdx.x;
    if (idx >= MROWS * DINNER) return;
    const int d = idx % DINNER;
    const int m = idx / DINNER;
    const int t = m % SEQLEN;

    float v = conv_b[d];
#pragma unroll
    for (int k = 0; k < DCONV; k++) {
        const int tt = t + k - (DCONV - 1);
        if (tt >= 0)
            v += conv_w[d * DCONV + k] * xz[(size_t)(m + tt - t) * (2 * DINNER) + d];
    }
    xc[idx] = silu_f(v);
}

// ---------------- chunked selective scan: thread-per-channel ----------------
// Block = 128 threads, each owning one d; 16 states in registers.
// Grid = (DINNER/128) * BATCH * NCH = 384 blocks.
#define SCB 128

__global__ __launch_bounds__(SCB)
void scan_phase1(const float* __restrict__ dt,
                 const float* __restrict__ xc,
                 const float* __restrict__ xdbl,
                 const float* __restrict__ A_log,
                 float* __restrict__ aprod_g,
                 float* __restrict__ hloc_g)
{
    __shared__ float Bsh[CHT][16];
    const int tid = threadIdx.x;
    const int dg = blockIdx.x % (DINNER / SCB);
    const int b  = (blockIdx.x / (DINNER / SCB)) % BATCH;
    const int c  =  blockIdx.x / ((DINNER / SCB) * BATCH);
    const int d  = dg * SCB + tid;
    const size_t m0 = (size_t)b * SEQLEN + c * CHT;

    for (int i = tid; i < CHT * 4; i += SCB) {
        const int r = i >> 2, qq = i & 3;
        *(float4*)&Bsh[r][qq * 4] =
            *(const float4*)&xdbl[(m0 + r) * XDBLW + DTRANK + qq * 4];
    }
    __syncthreads();

    float A[16];
    {
        const float4* ap = (const float4*)&A_log[(size_t)d * DSTATE];
#pragma unroll
        for (int i = 0; i < 4; i++) {
            const float4 v = ap[i];
            A[i*4+0] = -__expf(v.x); A[i*4+1] = -__expf(v.y);
            A[i*4+2] = -__expf(v.z); A[i*4+3] = -__expf(v.w);
        }
    }
    bool fast = true;
#pragma unroll
    for (int n = 0; n < 16; n++)
        fast = fast && (fabsf(A[n] + (float)(n + 1)) <= 1e-5f * (float)(n + 1));

    float h[16], ap[16];
#pragma unroll
    for (int n = 0; n < 16; n++) { h[n] = 0.f; ap[n] = 1.f; }

    if (fast) {
#pragma unroll 2
        for (int t = 0; t < CHT; t++) {
            const size_t m = m0 + t;
            const float dtv = dt[m * DINNER + d];
            const float du  = dtv * xc[m * DINNER + d];
            const float r1  = __expf(-dtv);
            float a = r1;
#pragma unroll
            for (int n = 0; n < 16; n++) {
                h[n] = a * h[n] + du * Bsh[t][n];
                ap[n] *= a;
                a *= r1;
            }
        }
    } else {
#pragma unroll 2
        for (int t = 0; t < CHT; t++) {
            const size_t m = m0 + t;
            const float dtv = dt[m * DINNER + d];
            const float du  = dtv * xc[m * DINNER + d];
#pragma unroll
            for (int n = 0; n < 16; n++) {
                const float a = __expf(dtv * A[n]);
                h[n] = a * h[n] + du * Bsh[t][n];
                ap[n] *= a;
            }
        }
    }

    const int bd = b * DINNER + d;
    float* po = &aprod_g[((size_t)bd * NCH + c) * DSTATE];
    float* ph = &hloc_g [((size_t)bd * NCH + c) * DSTATE];
#pragma unroll
    for (int i = 0; i < 4; i++) {
        *(float4*)&po[i*4] = make_float4(ap[i*4], ap[i*4+1], ap[i*4+2], ap[i*4+3]);
        *(float4*)&ph[i*4] = make_float4(h[i*4],  h[i*4+1],  h[i*4+2],  h[i*4+3]);
    }
}

__global__ __launch_bounds__(256)
void scan_phase2(const float* __restrict__ aprod_g,
                 const float* __restrict__ hloc_g,
                 float* __restrict__ h0_g)
{
    const int idx = blockIdx.x * blockDim.x + threadIdx.x;
    const int bd = idx >> 4;
    const int n  = idx & 15;
    if (bd >= NPAIRS) return;

    float h = 0.f;
#pragma unroll
    for (int c = 0; c < NCH; c++) {
        const size_t o = ((size_t)bd * NCH + c) * DSTATE + n;
        h0_g[o] = h;
        h = aprod_g[o] * h + hloc_g[o];
    }
}

__global__ __launch_bounds__(SCB)
void scan_phase3(const float* __restrict__ dt,
                 const float* __restrict__ xc,
                 const float* __restrict__ xdbl,
                 const float* __restrict__ A_log,
                 const float* __restrict__ h0_g,
                 float* __restrict__ y)
{
    __shared__ float Bsh[CHT][16];
    __shared__ float Csh[CHT][16];
    const int tid = threadIdx.x;
    const int dg = blockIdx.x % (DINNER / SCB);
    const int b  = (blockIdx.x / (DINNER / SCB)) % BATCH;
    const int c  =  blockIdx.x / ((DINNER / SCB) * BATCH);
    const int d  = dg * SCB + tid;
    const size_t m0 = (size_t)b * SEQLEN + c * CHT;

    for (int i = tid; i < CHT * 4; i += SCB) {
        const int r = i >> 2, qq = i & 3;
        *(float4*)&Bsh[r][qq * 4] =
            *(const float4*)&xdbl[(m0 + r) * XDBLW + DTRANK + qq * 4];
        *(float4*)&Csh[r][qq * 4] =
            *(const float4*)&xdbl[(m0 + r) * XDBLW + DTRANK + DSTATE + qq * 4];
    }
    __syncthreads();

    float A[16];
    {
        const float4* ap = (const float4*)&A_log[(size_t)d * DSTATE];
#pragma unroll
        for (int i = 0; i < 4; i++) {
            const float4 v = ap[i];
            A[i*4+0] = -__expf(v.x); A[i*4+1] = -__expf(v.y);
            A[i*4+2] = -__expf(v.z); A[i*4+3] = -__expf(v.w);
        }
    }
    bool fast = true;
#pragma unroll
    for (int n = 0; n < 16; n++)
        fast = fast && (fabsf(A[n] + (float)(n + 1)) <= 1e-5f * (float)(n + 1));

    const int bd = b * DINNER + d;
    float h[16];
    {
        const float4* hp = (const float4*)&h0_g[((size_t)bd * NCH + c) * DSTATE];
#pragma unroll
        for (int i = 0; i < 4; i++) {
            const float4 v = hp[i];
            h[i*4+0] = v.x; h[i*4+1] = v.y; h[i*4+2] = v.z; h[i*4+3] = v.w;
        }
    }

    if (fast) {
#pragma unroll 2
        for (int t = 0; t < CHT; t++) {
            const size_t m = m0 + t;
            const float dtv = dt[m * DINNER + d];
            const float du  = dtv * xc[m * DINNER + d];
            const float r1  = __expf(-dtv);
            float a = r1, p = 0.f;
#pragma unroll
            for (int n = 0; n < 16; n++) {
                h[n] = a * h[n] + du * Bsh[t][n];
                p += h[n] * Csh[t][n];
                a *= r1;
            }
            y[m * DINNER + d] = p;
        }
    } else {
#pragma unroll 2
        for (int t = 0; t < CHT; t++) {
            const size_t m = m0 + t;
            const float dtv = dt[m * DINNER + d];
            const float du  = dtv * xc[m * DINNER + d];
            float p = 0.f;
#pragma unroll
            for (int n = 0; n < 16; n++) {
                const float a = __expf(dtv * A[n]);
                h[n] = a * h[n] + du * Bsh[t][n];
                p += h[n] * Csh[t][n];
            }
            y[m * DINNER + d] = p;
        }
    }
}

// ---------------- combine ----------------
__global__ __launch_bounds__(256)
void combine_kernel(float* __restrict__ y,
                    const float* __restrict__ xc,
                    const float* __restrict__ xz,
                    const float* __restrict__ q,
                    const float* __restrict__ Dp)
{
    const int idx = blockIdx.x * blockDim.x + threadIdx.x;
    if (idx >= MROWS * DINNER) return;
    const int d = idx % DINNER;
    const int m = idx / DINNER;
    const float zv = xz[(size_t)m * (2 * DINNER) + DINNER + d];
    const float qv = q[idx];
    y[idx] = (y[idx] + xc[idx] * Dp[d]) * silu_f(zv) * silu_f(qv);
}

// ---------------- launch ----------------
extern "C" void kernel_launch(void* const* d_in, const int* in_sizes, int n_in,
                              void* d_out, int out_size)
{
    const float* hidden    = (const float*)d_in[0];
    const float* query     = (const float*)d_in[1];
    const float* in_proj_w = (const float*)d_in[2];
    const float* conv_w    = (const float*)d_in[3];
    const float* conv_b    = (const float*)d_in[4];
    const float* x_proj_w  = (const float*)d_in[5];
    const float* dt_proj_w = (const float*)d_in[6];
    const float* dt_proj_b = (const float*)d_in[7];
    const float* A_log     = (const float*)d_in[8];
    const float* Dp        = (const float*)d_in[9];
    const float* query_w   = (const float*)d_in[10];
    const float* query_b   = (const float*)d_in[11];
    const float* out_proj_w= (const float*)d_in[12];
    float* out = (float*)d_out;

    float *xz, *xc, *xdbl, *xp, *dt, *y, *q, *aprod, *hloc, *h0;
    cudaGetSymbolAddress((void**)&xz,    g_xz);
    cudaGetSymbolAddress((void**)&xc,    g_xc);
    cudaGetSymbolAddress((void**)&xdbl,  g_xdbl);
    cudaGetSymbolAddress((void**)&xp,    g_xp);
    cudaGetSymbolAddress((void**)&dt,    g_dt);
    cudaGetSymbolAddress((void**)&y,     g_y);
    cudaGetSymbolAddress((void**)&q,     g_q);
    cudaGetSymbolAddress((void**)&aprod, g_aprod);
    cudaGetSymbolAddress((void**)&hloc,  g_hloc);
    cudaGetSymbolAddress((void**)&h0,    g_h0);

    const int elemN = MROWS * DINNER;
    const int elemBlocks = (elemN + 255) / 256;

    // 1) xz = hidden @ in_proj_w^T        (4096 x 3072, K=768)
    gemm_tf32<<<dim3(2 * DINNER / TBN, MROWS / TBM, 1), 256>>>(
        hidden, DMODEL, in_proj_w, DMODEL, xz, 2 * DINNER,
        MROWS, 2 * DINNER, DMODEL, nullptr, 0, 0);

    // 2) causal conv + silu
    conv_silu_kernel<<<elemBlocks, 256>>>(xz, conv_w, conv_b, xc);

    // 3) x_dbl = xc @ x_proj_w^T          (4096 x 80, K=1536) split-K=4
    gemm_tf32<<<dim3(1, MROWS / TBM, SPLITK), 256>>>(
        xc, DINNER, x_proj_w, DINNER, xp, XDBLW,
        MROWS, XDBLW, DINNER, nullptr, 0, XPSTRIDE);
    reduce_xp<<<(MROWS * XDBLW + 255) / 256, 256>>>(xp, xdbl);

    // 4) dt = softplus(x_dbl[:, :48] @ dt_proj_w^T + b)   (4096 x 1536, K=48)
    gemm_tf32<<<dim3(DINNER / TBN, MROWS / TBM, 1), 256>>>(
        xdbl, XDBLW, dt_proj_w, DTRANK, dt, DINNER,
        MROWS, DINNER, DTRANK, dt_proj_b, 1, 0);

    // 5) q = query @ query_w^T + query_b  (4096 x 1536, K=768)
    gemm_tf32<<<dim3(DINNER / TBN, MROWS / TBM, 1), 256>>>(
        query, DMODEL, query_w, DMODEL, q, DINNER,
        MROWS, DINNER, DMODEL, query_b, 2, 0);

    // 6) chunked selective scan
    {
        const int nblk = (DINNER / SCB) * BATCH * NCH;   // 384
        scan_phase1<<<nblk, SCB>>>(dt, xc, xdbl, A_log, aprod, hloc);
        scan_phase2<<<(NPAIRS * DSTATE) / 256, 256>>>(aprod, hloc, h0);
        scan_phase3<<<nblk, SCB>>>(dt, xc, xdbl, A_log, h0, y);
    }

    // 7) combine gates
    combine_kernel<<<elemBlocks, 256>>>(y, xc, xz, q, Dp);

    // 8) out = y @ out_proj_w^T           (4096 x 768, K=1536)
    gemm_tf32<<<dim3(DMODEL / TBN, MROWS / TBM, 1), 256>>>(
        y, DINNER, out_proj_w, DINNER, out, DMODEL,
        MROWS, DMODEL, DINNER, nullptr, 0, 0);
}